// round 8
// baseline (speedup 1.0000x reference)
#include <cuda_runtime.h>
#include <cuda_fp16.h>
#include <cstdint>

// GCN link prediction, round 8:
//  - software-pipelined neighbor-index prefetch in both gather loops
//  - decode: 4 lanes/edge + shfl reduction (coalesced z-row loads)
//  - padded adjacency (CAP=128), fp16 y rows, fused epilogues (as R7)

#define NMAX  100000
#define EMAX  3200000
#define F_IN  128
#define H1    32
#define H2    16
#define CAP   128
#define CAPSH 7

__device__ __align__(16) int    g_cnt [NMAX];
__device__ __align__(16) int    g_epad[NMAX * CAP];
__device__ __align__(16) __half g_y1h[NMAX * H1];
__device__ __align__(16) __half g_y2h[NMAX * H2];
__device__ __align__(16) float  g_z  [NMAX * H2];

__device__ __forceinline__ void fma2(unsigned long long& acc,
                                     unsigned long long a, unsigned long long b) {
    asm("fma.rn.f32x2 %0, %1, %2, %0;" : "+l"(acc) : "l"(a), "l"(b));
}
__device__ __forceinline__ unsigned long long pack2(float lo, float hi) {
    unsigned long long r;
    asm("mov.b64 %0, {%1, %2};" : "=l"(r) : "f"(lo), "f"(hi));
    return r;
}
__device__ __forceinline__ float2 unpack2(unsigned long long v) {
    float2 r;
    asm("mov.b64 {%0, %1}, %2;" : "=f"(r.x), "=f"(r.y) : "l"(v));
    return r;
}
__device__ __forceinline__ uint32_t h2bits(float a, float b) {
    __half2 h = __floats2half2_rn(a, b);
    return *(uint32_t*)&h;
}
__device__ __forceinline__ float2 bits2f(uint32_t u) {
    return __half22float2(*(__half2*)&u);
}

// ---------------------------------------------------------------------------
__global__ void __launch_bounds__(256) k_fill(const int* __restrict__ src,
                                              const int* __restrict__ dst, int E) {
    int t = blockIdx.x * 256 + threadIdx.x;
    if (t * 8 >= E) return;
    int4 d0 = ((const int4*)dst)[t * 2];
    int4 d1 = ((const int4*)dst)[t * 2 + 1];
    int4 s0 = ((const int4*)src)[t * 2];
    int4 s1 = ((const int4*)src)[t * 2 + 1];

    int dd[8] = {d0.x, d0.y, d0.z, d0.w, d1.x, d1.y, d1.z, d1.w};
    int ss[8] = {s0.x, s0.y, s0.z, s0.w, s1.x, s1.y, s1.z, s1.w};

    int pos[8];
    #pragma unroll
    for (int u = 0; u < 8; u++) pos[u] = atomicAdd(&g_cnt[dd[u]], 1);
    #pragma unroll
    for (int u = 0; u < 8; u++) {
        int p = pos[u] < CAP ? pos[u] : (CAP - 1);
        g_epad[(dd[u] << CAPSH) + p] = ss[u];
    }
}

// ---------------------------------------------------------------------------
// GEMM1: y1h[n,32] = fp16( rsqrt(deg+1) * (x[n,128] @ W1[128,32]) )
__global__ void __launch_bounds__(256) k_gemm1(const float* __restrict__ x,
                                               const float* __restrict__ W1, int n) {
    __shared__ ulonglong2 Ws[F_IN * 8];
    int tid = threadIdx.x;
    const ulonglong2* W1u = (const ulonglong2*)W1;
    #pragma unroll 4
    for (int i = tid; i < F_IN * 8; i += 256) Ws[i] = W1u[i];
    __syncthreads();

    int node = blockIdx.x * 256 + tid;
    if (node >= n) return;

    const float4* xr = (const float4*)(x + (size_t)node * F_IN);

    unsigned long long acc[16];
    #pragma unroll
    for (int i = 0; i < 16; i++) acc[i] = 0ull;

    #pragma unroll
    for (int chunk = 0; chunk < 4; chunk++) {
        float4 xv[8];
        #pragma unroll
        for (int p = 0; p < 8; p++) xv[p] = xr[chunk * 8 + p];
        #pragma unroll
        for (int p = 0; p < 8; p++) {
            float xk[4] = {xv[p].x, xv[p].y, xv[p].z, xv[p].w};
            #pragma unroll
            for (int kk = 0; kk < 4; kk++) {
                int k = chunk * 32 + p * 4 + kk;
                unsigned long long xp = pack2(xk[kk], xk[kk]);
                #pragma unroll
                for (int q = 0; q < 8; q++) {
                    ulonglong2 w = Ws[k * 8 + q];
                    fma2(acc[q * 2],     xp, w.x);
                    fma2(acc[q * 2 + 1], xp, w.y);
                }
            }
        }
    }

    float is = rsqrtf((float)g_cnt[node] + 1.0f);
    uint4* yv = (uint4*)(g_y1h + (size_t)node * H1);
    #pragma unroll
    for (int q4 = 0; q4 < 4; q4++) {
        float2 a = unpack2(acc[q4 * 4 + 0]);
        float2 b = unpack2(acc[q4 * 4 + 1]);
        float2 c = unpack2(acc[q4 * 4 + 2]);
        float2 d = unpack2(acc[q4 * 4 + 3]);
        uint4 o;
        o.x = h2bits(a.x * is, a.y * is);
        o.y = h2bits(b.x * is, b.y * is);
        o.z = h2bits(c.x * is, c.y * is);
        o.w = h2bits(d.x * is, d.y * is);
        yv[q4] = o;
    }
}

// ---------------------------------------------------------------------------
// gather1 (fp16) + fused relu/bias + GEMM2 -> y2h fp16
// 4 lanes/node, 64 nodes/block; pipelined 8-edge unroll, int4 index loads
__global__ void __launch_bounds__(256) k_gather1(const float* __restrict__ b1,
                                                 const float* __restrict__ W2, int n) {
    __shared__ float Ws[H1 * H2];
    __shared__ float bs[H1];
    __shared__ float hs[64][H1 + 2];

    int tid = threadIdx.x;
    if (tid < H1 * H2 / 2) ((float2*)Ws)[tid] = ((const float2*)W2)[tid];
    if (tid < H1) bs[tid] = b1[tid];
    __syncthreads();

    int g = tid >> 2;
    int c = tid & 3;
    int node = blockIdx.x * 64 + g;

    float acc[8];
    #pragma unroll
    for (int i = 0; i < 8; i++) acc[i] = 0.f;
    float is = 0.f;
    int deg = 0;
    const uint4* y1v = (const uint4*)g_y1h;
    const int4* epad4 = (const int4*)g_epad;
    int base4 = (node << CAPSH) >> 2;

    if (node < n) {
        uint4 self = y1v[node * 4 + c];
        float2 f0 = bits2f(self.x), f1 = bits2f(self.y), f2 = bits2f(self.z), f3 = bits2f(self.w);
        acc[0] = f0.x; acc[1] = f0.y; acc[2] = f1.x; acc[3] = f1.y;
        acc[4] = f2.x; acc[5] = f2.y; acc[6] = f3.x; acc[7] = f3.y;
        deg = g_cnt[node];
        is = rsqrtf((float)deg + 1.0f);
    }

    int4 i0, i1;
    if (deg >= 8) {
        i0 = __ldg(&epad4[base4]);
        i1 = __ldg(&epad4[base4 + 1]);
    }
    int j = 0;
    for (; j + 8 <= deg; j += 8) {
        int s[8] = {i0.x, i0.y, i0.z, i0.w, i1.x, i1.y, i1.z, i1.w};
        // prefetch next indices before consuming current gathers
        if (j + 16 <= deg) {
            i0 = __ldg(&epad4[base4 + (j >> 2) + 2]);
            i1 = __ldg(&epad4[base4 + (j >> 2) + 3]);
        }
        uint4 v[8];
        #pragma unroll
        for (int u = 0; u < 8; u++) v[u] = y1v[s[u] * 4 + c];
        #pragma unroll
        for (int u = 0; u < 8; u++) {
            float2 f0 = bits2f(v[u].x), f1 = bits2f(v[u].y),
                   f2 = bits2f(v[u].z), f3 = bits2f(v[u].w);
            acc[0] += f0.x; acc[1] += f0.y; acc[2] += f1.x; acc[3] += f1.y;
            acc[4] += f2.x; acc[5] += f2.y; acc[6] += f3.x; acc[7] += f3.y;
        }
    }
    if (j < deg) {
        int4 t0 = __ldg(&epad4[base4 + (j >> 2)]);
        int4 t1 = __ldg(&epad4[base4 + (j >> 2) + 1]);
        int s[8] = {t0.x, t0.y, t0.z, t0.w, t1.x, t1.y, t1.z, t1.w};
        int rem = deg - j;
        #pragma unroll
        for (int u = 0; u < 8; u++) {
            if (u < rem) {
                uint4 v0 = y1v[s[u] * 4 + c];
                float2 f0 = bits2f(v0.x), f1 = bits2f(v0.y),
                       f2 = bits2f(v0.z), f3 = bits2f(v0.w);
                acc[0] += f0.x; acc[1] += f0.y; acc[2] += f1.x; acc[3] += f1.y;
                acc[4] += f2.x; acc[5] += f2.y; acc[6] += f3.x; acc[7] += f3.y;
            }
        }
    }

    #pragma unroll
    for (int u = 0; u < 8; u++)
        hs[g][c * 8 + u] = fmaxf(fmaf(is, acc[u], bs[c * 8 + u]), 0.f);
    __syncthreads();

    if (node >= n) return;
    float a0 = 0.f, a1 = 0.f, a2 = 0.f, a3 = 0.f;
    #pragma unroll
    for (int k = 0; k < H1; k++) {
        float h = hs[g][k];
        a0 = fmaf(h, Ws[k * H2 + c * 4 + 0], a0);
        a1 = fmaf(h, Ws[k * H2 + c * 4 + 1], a1);
        a2 = fmaf(h, Ws[k * H2 + c * 4 + 2], a2);
        a3 = fmaf(h, Ws[k * H2 + c * 4 + 3], a3);
    }
    uint2 o;
    o.x = h2bits(a0 * is, a1 * is);
    o.y = h2bits(a2 * is, a3 * is);
    ((uint2*)(g_y2h + (size_t)node * H2))[c] = o;
}

// ---------------------------------------------------------------------------
// gather2 (fp16) + fused bias -> z fp32
// 2 lanes/node, 128 nodes/block; pipelined 8-edge unroll, int4 index loads
__global__ void __launch_bounds__(256) k_gather2(const float* __restrict__ b2, int n) {
    __shared__ float bs[H2];
    if (threadIdx.x < H2) bs[threadIdx.x] = b2[threadIdx.x];
    __syncthreads();

    int tid = threadIdx.x;
    int g = tid >> 1;
    int c = tid & 1;
    int node = blockIdx.x * 128 + g;
    if (node >= n) return;

    const uint4* y2v = (const uint4*)g_y2h;
    const int4* epad4 = (const int4*)g_epad;
    int base4 = (node << CAPSH) >> 2;

    uint4 self = y2v[node * 2 + c];
    float acc[8];
    {
        float2 f0 = bits2f(self.x), f1 = bits2f(self.y), f2 = bits2f(self.z), f3 = bits2f(self.w);
        acc[0] = f0.x; acc[1] = f0.y; acc[2] = f1.x; acc[3] = f1.y;
        acc[4] = f2.x; acc[5] = f2.y; acc[6] = f3.x; acc[7] = f3.y;
    }
    int deg = g_cnt[node];
    float is = rsqrtf((float)deg + 1.0f);

    int4 i0, i1;
    if (deg >= 8) {
        i0 = __ldg(&epad4[base4]);
        i1 = __ldg(&epad4[base4 + 1]);
    }
    int j = 0;
    for (; j + 8 <= deg; j += 8) {
        int s[8] = {i0.x, i0.y, i0.z, i0.w, i1.x, i1.y, i1.z, i1.w};
        if (j + 16 <= deg) {
            i0 = __ldg(&epad4[base4 + (j >> 2) + 2]);
            i1 = __ldg(&epad4[base4 + (j >> 2) + 3]);
        }
        uint4 v[8];
        #pragma unroll
        for (int u = 0; u < 8; u++) v[u] = y2v[s[u] * 2 + c];
        #pragma unroll
        for (int u = 0; u < 8; u++) {
            float2 f0 = bits2f(v[u].x), f1 = bits2f(v[u].y),
                   f2 = bits2f(v[u].z), f3 = bits2f(v[u].w);
            acc[0] += f0.x; acc[1] += f0.y; acc[2] += f1.x; acc[3] += f1.y;
            acc[4] += f2.x; acc[5] += f2.y; acc[6] += f3.x; acc[7] += f3.y;
        }
    }
    if (j < deg) {
        int4 t0 = __ldg(&epad4[base4 + (j >> 2)]);
        int4 t1 = __ldg(&epad4[base4 + (j >> 2) + 1]);
        int s[8] = {t0.x, t0.y, t0.z, t0.w, t1.x, t1.y, t1.z, t1.w};
        int rem = deg - j;
        #pragma unroll
        for (int u = 0; u < 8; u++) {
            if (u < rem) {
                uint4 v0 = y2v[s[u] * 2 + c];
                float2 f0 = bits2f(v0.x), f1 = bits2f(v0.y),
                       f2 = bits2f(v0.z), f3 = bits2f(v0.w);
                acc[0] += f0.x; acc[1] += f0.y; acc[2] += f1.x; acc[3] += f1.y;
                acc[4] += f2.x; acc[5] += f2.y; acc[6] += f3.x; acc[7] += f3.y;
            }
        }
    }

    float* zr = g_z + (size_t)node * H2 + c * 8;
    float4 z0, z1;
    z0.x = fmaf(is, acc[0], bs[c*8+0]); z0.y = fmaf(is, acc[1], bs[c*8+1]);
    z0.z = fmaf(is, acc[2], bs[c*8+2]); z0.w = fmaf(is, acc[3], bs[c*8+3]);
    z1.x = fmaf(is, acc[4], bs[c*8+4]); z1.y = fmaf(is, acc[5], bs[c*8+5]);
    z1.z = fmaf(is, acc[6], bs[c*8+6]); z1.w = fmaf(is, acc[7], bs[c*8+7]);
    ((float4*)zr)[0] = z0;
    ((float4*)zr)[1] = z1;
}

// ---------------------------------------------------------------------------
// decode: 4 lanes per edge; coalesced float4 row loads + shfl reduce
__global__ void __launch_bounds__(256) k_decode(const int* __restrict__ ea,
                                                const int* __restrict__ eb,
                                                float* __restrict__ out, int L) {
    int t = blockIdx.x * 256 + threadIdx.x;
    int e = t >> 2;
    if (e >= L) return;
    int c = t & 3;
    int a = __ldg(&ea[e]);
    int b = __ldg(&eb[e]);
    float4 u = ((const float4*)g_z)[a * 4 + c];
    float4 v = ((const float4*)g_z)[b * 4 + c];
    float s = u.x * v.x + u.y * v.y + u.z * v.z + u.w * v.w;
    s += __shfl_xor_sync(0xffffffffu, s, 1);
    s += __shfl_xor_sync(0xffffffffu, s, 2);
    if (c == 0) out[e] = s;
}

// ---------------------------------------------------------------------------
extern "C" void kernel_launch(void* const* d_in, const int* in_sizes, int n_in,
                              void* d_out, int out_size) {
    const float* x   = (const float*)d_in[0];
    const int*   ei  = (const int*)  d_in[1];
    const int*   eli = (const int*)  d_in[2];
    const float* W1  = (const float*)d_in[3];
    const float* b1  = (const float*)d_in[4];
    const float* W2  = (const float*)d_in[5];
    const float* b2  = (const float*)d_in[6];
    float* out = (float*)d_out;

    int n = in_sizes[0] / F_IN;     // 100000
    int E = in_sizes[1] / 2;        // 3200000
    int L = in_sizes[2] / 2;        // 200000

    const int* src = ei;
    const int* dst = ei + E;
    const int* ea  = eli;
    const int* eb  = eli + L;

    int E8 = E / 8;

    void* cntPtr = nullptr;
    cudaGetSymbolAddress(&cntPtr, g_cnt);
    cudaMemsetAsync(cntPtr, 0, (size_t)n * sizeof(int));

    k_fill    <<<(E8 + 255) / 256, 256>>>(src, dst, E);

    k_gemm1   <<<(n + 255) / 256, 256>>>(x, W1, n);
    k_gather1 <<<(n + 63) / 64, 256>>>(b1, W2, n);
    k_gather2 <<<(n + 127) / 128, 256>>>(b2, n);

    k_decode  <<<((L * 4) + 255) / 256, 256>>>(ea, eb, out, L);
}

// round 9
// speedup vs baseline: 1.1395x; 1.1395x over previous
#include <cuda_runtime.h>
#include <cuda_fp16.h>
#include <cstdint>

// GCN link prediction, round 9:
//  - fill and gemm1 fused into ONE kernel via block-range split (overlap
//    atomic/store pipe with FMA pipe); gemm1 stores UNNORMALIZED xW rows,
//    small k_norm1 applies rsqrt(deg+1) afterwards
//  - gathers: R7 form (no prefetch pipelining — R8 showed it regresses)
//  - decode: 4 lanes/edge + shfl reduce

#define NMAX  100000
#define EMAX  3200000
#define F_IN  128
#define H1    32
#define H2    16
#define CAP   128
#define CAPSH 7

__device__ __align__(16) int    g_cnt [NMAX];
__device__ __align__(16) int    g_epad[NMAX * CAP];
__device__ __align__(16) __half g_y1h[NMAX * H1];
__device__ __align__(16) __half g_y2h[NMAX * H2];
__device__ __align__(16) float  g_z  [NMAX * H2];

__device__ __forceinline__ void fma2(unsigned long long& acc,
                                     unsigned long long a, unsigned long long b) {
    asm("fma.rn.f32x2 %0, %1, %2, %0;" : "+l"(acc) : "l"(a), "l"(b));
}
__device__ __forceinline__ unsigned long long pack2(float lo, float hi) {
    unsigned long long r;
    asm("mov.b64 %0, {%1, %2};" : "=l"(r) : "f"(lo), "f"(hi));
    return r;
}
__device__ __forceinline__ float2 unpack2(unsigned long long v) {
    float2 r;
    asm("mov.b64 {%0, %1}, %2;" : "=f"(r.x), "=f"(r.y) : "l"(v));
    return r;
}
__device__ __forceinline__ uint32_t h2bits(float a, float b) {
    __half2 h = __floats2half2_rn(a, b);
    return *(uint32_t*)&h;
}
__device__ __forceinline__ float2 bits2f(uint32_t u) {
    return __half22float2(*(__half2*)&u);
}

// ---------------------------------------------------------------------------
// fused gemm1 (blocks [0, gemmBlocks)) + fill (remaining blocks)
__global__ void __launch_bounds__(256) k_fuse(const float* __restrict__ x,
                                              const float* __restrict__ W1,
                                              const int* __restrict__ src,
                                              const int* __restrict__ dst,
                                              int n, int E, int gemmBlocks) {
    __shared__ ulonglong2 Ws[F_IN * 8];     // 16KB (unused by fill blocks)
    int tid = threadIdx.x;

    if (blockIdx.x < gemmBlocks) {
        // ---- GEMM1: y1h[n,32] = fp16(x[n,128] @ W1[128,32])  (no norm) ----
        const ulonglong2* W1u = (const ulonglong2*)W1;
        #pragma unroll 4
        for (int i = tid; i < F_IN * 8; i += 256) Ws[i] = W1u[i];
        __syncthreads();

        int node = blockIdx.x * 256 + tid;
        if (node >= n) return;

        const float4* xr = (const float4*)(x + (size_t)node * F_IN);

        unsigned long long acc[16];
        #pragma unroll
        for (int i = 0; i < 16; i++) acc[i] = 0ull;

        #pragma unroll
        for (int chunk = 0; chunk < 4; chunk++) {
            float4 xv[8];
            #pragma unroll
            for (int p = 0; p < 8; p++) xv[p] = xr[chunk * 8 + p];
            #pragma unroll
            for (int p = 0; p < 8; p++) {
                float xk[4] = {xv[p].x, xv[p].y, xv[p].z, xv[p].w};
                #pragma unroll
                for (int kk = 0; kk < 4; kk++) {
                    int k = chunk * 32 + p * 4 + kk;
                    unsigned long long xp = pack2(xk[kk], xk[kk]);
                    #pragma unroll
                    for (int q = 0; q < 8; q++) {
                        ulonglong2 w = Ws[k * 8 + q];
                        fma2(acc[q * 2],     xp, w.x);
                        fma2(acc[q * 2 + 1], xp, w.y);
                    }
                }
            }
        }

        uint4* yv = (uint4*)(g_y1h + (size_t)node * H1);
        #pragma unroll
        for (int q4 = 0; q4 < 4; q4++) {
            float2 a = unpack2(acc[q4 * 4 + 0]);
            float2 b = unpack2(acc[q4 * 4 + 1]);
            float2 c = unpack2(acc[q4 * 4 + 2]);
            float2 d = unpack2(acc[q4 * 4 + 3]);
            uint4 o;
            o.x = h2bits(a.x, a.y);
            o.y = h2bits(b.x, b.y);
            o.z = h2bits(c.x, c.y);
            o.w = h2bits(d.x, d.y);
            yv[q4] = o;
        }
    } else {
        // ---- fill: padded adjacency via atomic cursors ----
        int t = (blockIdx.x - gemmBlocks) * 256 + tid;
        if (t * 8 >= E) return;
        int4 d0 = ((const int4*)dst)[t * 2];
        int4 d1 = ((const int4*)dst)[t * 2 + 1];
        int4 s0 = ((const int4*)src)[t * 2];
        int4 s1 = ((const int4*)src)[t * 2 + 1];

        int dd[8] = {d0.x, d0.y, d0.z, d0.w, d1.x, d1.y, d1.z, d1.w};
        int ss[8] = {s0.x, s0.y, s0.z, s0.w, s1.x, s1.y, s1.z, s1.w};

        int pos[8];
        #pragma unroll
        for (int u = 0; u < 8; u++) pos[u] = atomicAdd(&g_cnt[dd[u]], 1);
        #pragma unroll
        for (int u = 0; u < 8; u++) {
            int p = pos[u] < CAP ? pos[u] : (CAP - 1);
            g_epad[(dd[u] << CAPSH) + p] = ss[u];
        }
    }
}

// ---------------------------------------------------------------------------
// norm1: y1h[node] *= rsqrt(deg+1); 4 threads/node (uint4 = 8 halves each)
__global__ void __launch_bounds__(256) k_norm1(int n) {
    int t = blockIdx.x * 256 + threadIdx.x;
    int node = t >> 2;
    if (node >= n) return;
    int c = t & 3;
    float is = rsqrtf((float)g_cnt[node] + 1.0f);
    uint4* yv = (uint4*)(g_y1h + (size_t)node * H1);
    uint4 v = yv[c];
    float2 f0 = bits2f(v.x), f1 = bits2f(v.y), f2 = bits2f(v.z), f3 = bits2f(v.w);
    uint4 o;
    o.x = h2bits(f0.x * is, f0.y * is);
    o.y = h2bits(f1.x * is, f1.y * is);
    o.z = h2bits(f2.x * is, f2.y * is);
    o.w = h2bits(f3.x * is, f3.y * is);
    yv[c] = o;
}

// ---------------------------------------------------------------------------
// gather1 (fp16) + fused relu/bias + GEMM2 -> y2h fp16   (R7 form)
__global__ void __launch_bounds__(256) k_gather1(const float* __restrict__ b1,
                                                 const float* __restrict__ W2, int n) {
    __shared__ float Ws[H1 * H2];
    __shared__ float bs[H1];
    __shared__ float hs[64][H1 + 2];

    int tid = threadIdx.x;
    if (tid < H1 * H2 / 2) ((float2*)Ws)[tid] = ((const float2*)W2)[tid];
    if (tid < H1) bs[tid] = b1[tid];
    __syncthreads();

    int g = tid >> 2;
    int c = tid & 3;
    int node = blockIdx.x * 64 + g;

    float acc[8];
    #pragma unroll
    for (int i = 0; i < 8; i++) acc[i] = 0.f;
    float is = 0.f;
    int deg = 0;
    const uint4* y1v = (const uint4*)g_y1h;
    const int4* epad4 = (const int4*)g_epad;
    int base4 = (node << CAPSH) >> 2;

    if (node < n) {
        uint4 self = y1v[node * 4 + c];
        float2 f0 = bits2f(self.x), f1 = bits2f(self.y), f2 = bits2f(self.z), f3 = bits2f(self.w);
        acc[0] = f0.x; acc[1] = f0.y; acc[2] = f1.x; acc[3] = f1.y;
        acc[4] = f2.x; acc[5] = f2.y; acc[6] = f3.x; acc[7] = f3.y;
        deg = g_cnt[node];
        is = rsqrtf((float)deg + 1.0f);
    }

    int j = 0;
    for (; j + 8 <= deg; j += 8) {
        int4 i0 = __ldg(&epad4[base4 + (j >> 2)]);
        int4 i1 = __ldg(&epad4[base4 + (j >> 2) + 1]);
        int s[8] = {i0.x, i0.y, i0.z, i0.w, i1.x, i1.y, i1.z, i1.w};
        uint4 v[8];
        #pragma unroll
        for (int u = 0; u < 8; u++) v[u] = y1v[s[u] * 4 + c];
        #pragma unroll
        for (int u = 0; u < 8; u++) {
            float2 f0 = bits2f(v[u].x), f1 = bits2f(v[u].y),
                   f2 = bits2f(v[u].z), f3 = bits2f(v[u].w);
            acc[0] += f0.x; acc[1] += f0.y; acc[2] += f1.x; acc[3] += f1.y;
            acc[4] += f2.x; acc[5] += f2.y; acc[6] += f3.x; acc[7] += f3.y;
        }
    }
    if (j < deg) {
        int4 i0 = __ldg(&epad4[base4 + (j >> 2)]);
        int4 i1 = __ldg(&epad4[base4 + (j >> 2) + 1]);
        int s[8] = {i0.x, i0.y, i0.z, i0.w, i1.x, i1.y, i1.z, i1.w};
        int rem = deg - j;
        #pragma unroll
        for (int u = 0; u < 8; u++) {
            if (u < rem) {
                uint4 v0 = y1v[s[u] * 4 + c];
                float2 f0 = bits2f(v0.x), f1 = bits2f(v0.y),
                       f2 = bits2f(v0.z), f3 = bits2f(v0.w);
                acc[0] += f0.x; acc[1] += f0.y; acc[2] += f1.x; acc[3] += f1.y;
                acc[4] += f2.x; acc[5] += f2.y; acc[6] += f3.x; acc[7] += f3.y;
            }
        }
    }

    #pragma unroll
    for (int u = 0; u < 8; u++)
        hs[g][c * 8 + u] = fmaxf(fmaf(is, acc[u], bs[c * 8 + u]), 0.f);
    __syncthreads();

    if (node >= n) return;
    float a0 = 0.f, a1 = 0.f, a2 = 0.f, a3 = 0.f;
    #pragma unroll
    for (int k = 0; k < H1; k++) {
        float h = hs[g][k];
        a0 = fmaf(h, Ws[k * H2 + c * 4 + 0], a0);
        a1 = fmaf(h, Ws[k * H2 + c * 4 + 1], a1);
        a2 = fmaf(h, Ws[k * H2 + c * 4 + 2], a2);
        a3 = fmaf(h, Ws[k * H2 + c * 4 + 3], a3);
    }
    uint2 o;
    o.x = h2bits(a0 * is, a1 * is);
    o.y = h2bits(a2 * is, a3 * is);
    ((uint2*)(g_y2h + (size_t)node * H2))[c] = o;
}

// ---------------------------------------------------------------------------
// gather2 (fp16) + fused bias -> z fp32   (R7 form)
__global__ void __launch_bounds__(256) k_gather2(const float* __restrict__ b2, int n) {
    __shared__ float bs[H2];
    if (threadIdx.x < H2) bs[threadIdx.x] = b2[threadIdx.x];
    __syncthreads();

    int tid = threadIdx.x;
    int g = tid >> 1;
    int c = tid & 1;
    int node = blockIdx.x * 128 + g;
    if (node >= n) return;

    const uint4* y2v = (const uint4*)g_y2h;
    const int4* epad4 = (const int4*)g_epad;
    int base4 = (node << CAPSH) >> 2;

    uint4 self = y2v[node * 2 + c];
    float acc[8];
    {
        float2 f0 = bits2f(self.x), f1 = bits2f(self.y), f2 = bits2f(self.z), f3 = bits2f(self.w);
        acc[0] = f0.x; acc[1] = f0.y; acc[2] = f1.x; acc[3] = f1.y;
        acc[4] = f2.x; acc[5] = f2.y; acc[6] = f3.x; acc[7] = f3.y;
    }
    int deg = g_cnt[node];
    float is = rsqrtf((float)deg + 1.0f);

    int j = 0;
    for (; j + 8 <= deg; j += 8) {
        int4 i0 = __ldg(&epad4[base4 + (j >> 2)]);
        int4 i1 = __ldg(&epad4[base4 + (j >> 2) + 1]);
        int s[8] = {i0.x, i0.y, i0.z, i0.w, i1.x, i1.y, i1.z, i1.w};
        uint4 v[8];
        #pragma unroll
        for (int u = 0; u < 8; u++) v[u] = y2v[s[u] * 2 + c];
        #pragma unroll
        for (int u = 0; u < 8; u++) {
            float2 f0 = bits2f(v[u].x), f1 = bits2f(v[u].y),
                   f2 = bits2f(v[u].z), f3 = bits2f(v[u].w);
            acc[0] += f0.x; acc[1] += f0.y; acc[2] += f1.x; acc[3] += f1.y;
            acc[4] += f2.x; acc[5] += f2.y; acc[6] += f3.x; acc[7] += f3.y;
        }
    }
    if (j < deg) {
        int4 i0 = __ldg(&epad4[base4 + (j >> 2)]);
        int4 i1 = __ldg(&epad4[base4 + (j >> 2) + 1]);
        int s[8] = {i0.x, i0.y, i0.z, i0.w, i1.x, i1.y, i1.z, i1.w};
        int rem = deg - j;
        #pragma unroll
        for (int u = 0; u < 8; u++) {
            if (u < rem) {
                uint4 v0 = y2v[s[u] * 2 + c];
                float2 f0 = bits2f(v0.x), f1 = bits2f(v0.y),
                       f2 = bits2f(v0.z), f3 = bits2f(v0.w);
                acc[0] += f0.x; acc[1] += f0.y; acc[2] += f1.x; acc[3] += f1.y;
                acc[4] += f2.x; acc[5] += f2.y; acc[6] += f3.x; acc[7] += f3.y;
            }
        }
    }

    float* zr = g_z + (size_t)node * H2 + c * 8;
    float4 z0, z1;
    z0.x = fmaf(is, acc[0], bs[c*8+0]); z0.y = fmaf(is, acc[1], bs[c*8+1]);
    z0.z = fmaf(is, acc[2], bs[c*8+2]); z0.w = fmaf(is, acc[3], bs[c*8+3]);
    z1.x = fmaf(is, acc[4], bs[c*8+4]); z1.y = fmaf(is, acc[5], bs[c*8+5]);
    z1.z = fmaf(is, acc[6], bs[c*8+6]); z1.w = fmaf(is, acc[7], bs[c*8+7]);
    ((float4*)zr)[0] = z0;
    ((float4*)zr)[1] = z1;
}

// ---------------------------------------------------------------------------
// decode: 4 lanes per edge; coalesced float4 row loads + shfl reduce
__global__ void __launch_bounds__(256) k_decode(const int* __restrict__ ea,
                                                const int* __restrict__ eb,
                                                float* __restrict__ out, int L) {
    int t = blockIdx.x * 256 + threadIdx.x;
    int e = t >> 2;
    if (e >= L) return;
    int c = t & 3;
    int a = __ldg(&ea[e]);
    int b = __ldg(&eb[e]);
    float4 u = ((const float4*)g_z)[a * 4 + c];
    float4 v = ((const float4*)g_z)[b * 4 + c];
    float s = u.x * v.x + u.y * v.y + u.z * v.z + u.w * v.w;
    s += __shfl_xor_sync(0xffffffffu, s, 1);
    s += __shfl_xor_sync(0xffffffffu, s, 2);
    if (c == 0) out[e] = s;
}

// ---------------------------------------------------------------------------
extern "C" void kernel_launch(void* const* d_in, const int* in_sizes, int n_in,
                              void* d_out, int out_size) {
    const float* x   = (const float*)d_in[0];
    const int*   ei  = (const int*)  d_in[1];
    const int*   eli = (const int*)  d_in[2];
    const float* W1  = (const float*)d_in[3];
    const float* b1  = (const float*)d_in[4];
    const float* W2  = (const float*)d_in[5];
    const float* b2  = (const float*)d_in[6];
    float* out = (float*)d_out;

    int n = in_sizes[0] / F_IN;     // 100000
    int E = in_sizes[1] / 2;        // 3200000
    int L = in_sizes[2] / 2;        // 200000

    const int* src = ei;
    const int* dst = ei + E;
    const int* ea  = eli;
    const int* eb  = eli + L;

    int gemmBlocks = (n + 255) / 256;            // 391
    int fillBlocks = (E / 8 + 255) / 256;        // 1563

    void* cntPtr = nullptr;
    cudaGetSymbolAddress(&cntPtr, g_cnt);
    cudaMemsetAsync(cntPtr, 0, (size_t)n * sizeof(int));

    k_fuse    <<<gemmBlocks + fillBlocks, 256>>>(x, W1, src, dst, n, E, gemmBlocks);
    k_norm1   <<<(n * 4 + 255) / 256, 256>>>(n);

    k_gather1 <<<(n + 63) / 64, 256>>>(b1, W2, n);
    k_gather2 <<<(n + 127) / 128, 256>>>(b2, n);

    k_decode  <<<((L * 4) + 255) / 256, 256>>>(ea, eb, out, L);
}